// round 8
// baseline (speedup 1.0000x reference)
#include <cuda_runtime.h>
#include <math.h>

#define FDIM   257
#define BB     16
#define CC     4
#define LL     160000
#define TT     1251
#define HOPC   128
#define ROW    (4*CC*FDIM)          // 4112 floats per (b,t)
#define SVLEN  (2*CC*FDIM)          // 2056

__device__ float g_win[512];
__device__ float g_sv[SVLEN];

// ---------------- setup: window + steering-vector tables ----------------
__global__ void setup_kernel(const float* __restrict__ angle,
                             const float* __restrict__ mic_pos)
{
    __shared__ float sK[CC];
    int tid = threadIdx.x;

    if (tid < 512) {
        float cp = cosf((2.0f * (float)M_PI / 512.0f) * (float)tid);
        g_win[tid] = 0.5f * (1.0f - cp);
    }
    if (tid < CC) {
        const float half_pi = 1.57079632679489662f;
        float s90 = sinf(half_pi);
        float c90 = cosf(half_pi);
        float dc = 0.0f, d0 = 0.0f;
        #pragma unroll
        for (int bb = 0; bb < BB; bb++) {
            float rad = -angle[bb] * ((float)M_PI / 180.0f);
            float lx = cosf(rad) * s90;
            float ly = sinf(rad) * s90;
            float lz = c90;
            const float* mp0 = mic_pos + (bb * CC + 0) * 3;
            const float* mpc = mic_pos + (bb * CC + tid) * 3;
            float e;
            e = mp0[0] - lx; d0 += e * e;
            e = mp0[1] - ly; d0 += e * e;
            e = mp0[2] - lz; d0 += e * e;
            e = mpc[0] - lx; dc += e * e;
            e = mpc[1] - ly; dc += e * e;
            e = mpc[2] - lz; dc += e * e;
        }
        float tdoa = sqrtf(dc) - sqrtf(d0);
        sK[tid] = (-2.0f * (float)M_PI * 16000.0f / (512.0f * 340.4f)) * tdoa;
    }
    __syncthreads();

    for (int idx = tid; idx < SVLEN; idx += blockDim.x) {
        int reim = idx / (CC * FDIM);
        int rem  = idx - reim * (CC * FDIM);
        int c    = rem / FDIM;
        int f    = rem - c * FDIM;
        float s, co;
        sincosf(sK[c] * (float)f, &s, &co);
        g_sv[idx] = 0.5f * (reim ? s : co);
    }
}

// ---------------- main: 2x packed radix-8 Stockham FFT per (b,t) ----------------
#define PIDX(i) ((i) + ((i) >> 3))    // pad every 8 floats -> conflict-free stage writes
#define FFT2(ar,ai,br,bi) { float _tr=(ar), _ti=(ai); (ar)=_tr+(br); (ai)=_ti+(bi); (br)=_tr-(br); (bi)=_ti-(bi); }

__global__ __launch_bounds__(128) void sf_kernel(const float* __restrict__ x,
                                                 float* __restrict__ out)
{
    // [fft][pingpong][re/im][576]
    __shared__ float sbuf[2][2][2][576];

    const int t   = blockIdx.x;
    const int b   = blockIdx.y;
    const int tid = threadIdx.x;
    const int fft = tid >> 6;     // 0: channels 0,1   1: channels 2,3
    const int j   = tid & 63;

    // ---- load frame (reflect pad) * hann, packed: re=ch(2f), im=ch(2f+1) ----
    {
        const float* xc0 = x + ((size_t)(b * CC) + 2 * fft    ) * LL;
        const float* xc1 = x + ((size_t)(b * CC) + 2 * fft + 1) * LL;
        const int base = t * HOPC - 256;
        #pragma unroll
        for (int k = 0; k < 8; k++) {
            int p = j + k * 64;
            int idx = base + p;
            if (idx < 0)   idx = -idx;
            if (idx >= LL) idx = 2 * (LL - 1) - idx;
            float w = g_win[p];
            sbuf[fft][0][0][PIDX(p)] = xc0[idx] * w;
            sbuf[fft][0][1][PIDX(p)] = xc1[idx] * w;
        }
    }
    __syncthreads();

    // ---- 3-stage radix-8 Stockham (Ns = 1, 8, 64), ping-pong buffers ----
    float vr[8], vi[8];
    const float S2 = 0.70710678118654752f;
    int src = 0;

    #pragma unroll
    for (int stage = 0; stage < 3; stage++) {
        const int Ns = (stage == 0) ? 1 : (stage == 1) ? 8 : 64;

        const float* re = sbuf[fft][src][0];
        const float* im = sbuf[fft][src][1];
        #pragma unroll
        for (int r = 0; r < 8; r++) {
            int a = PIDX(j + r * 64);
            vr[r] = re[a];
            vi[r] = im[a];
        }

        if (stage > 0) {
            // v[r] *= exp(-2*pi*i * r * (j mod Ns) / (8*Ns)) via power recurrence
            float ang = (-2.0f * (float)M_PI / (8.0f * (float)Ns)) * (float)(j & (Ns - 1));
            float ws, wc;
            sincosf(ang, &ws, &wc);
            float cr = wc, ci = ws;
            #pragma unroll
            for (int r = 1; r < 8; r++) {
                float tr = vr[r] * cr - vi[r] * ci;
                float ti = vr[r] * ci + vi[r] * cr;
                vr[r] = tr; vi[r] = ti;
                float ncr = cr * wc - ci * ws;
                float nci = cr * ws + ci * wc;
                cr = ncr; ci = nci;
            }
        }

        // ---- in-register 8-point DIF FFT (output bit-reversed) ----
        FFT2(vr[0], vi[0], vr[4], vi[4]);
        FFT2(vr[1], vi[1], vr[5], vi[5]);
        FFT2(vr[2], vi[2], vr[6], vi[6]);
        FFT2(vr[3], vi[3], vr[7], vi[7]);
        { float tr = (vr[5] + vi[5]) * S2; float ti = (vi[5] - vr[5]) * S2; vr[5] = tr; vi[5] = ti; } // *W8^1
        { float tr = vi[6]; vi[6] = -vr[6]; vr[6] = tr; }                                             // *-i
        { float tr = (vi[7] - vr[7]) * S2; float ti = -(vr[7] + vi[7]) * S2; vr[7] = tr; vi[7] = ti; }// *W8^3
        FFT2(vr[0], vi[0], vr[2], vi[2]);
        FFT2(vr[1], vi[1], vr[3], vi[3]);
        FFT2(vr[4], vi[4], vr[6], vi[6]);
        FFT2(vr[5], vi[5], vr[7], vi[7]);
        { float tr = vi[3]; vi[3] = -vr[3]; vr[3] = tr; }
        { float tr = vi[7]; vi[7] = -vr[7]; vr[7] = tr; }
        FFT2(vr[0], vi[0], vr[1], vi[1]);
        FFT2(vr[2], vi[2], vr[3], vi[3]);
        FFT2(vr[4], vi[4], vr[5], vi[5]);
        FFT2(vr[6], vi[6], vr[7], vi[7]);

        // ---- scatter: dst[idxD + r*Ns] = X[r] = v[brev3(r)] ----
        float* dre = sbuf[fft][src ^ 1][0];
        float* dim_ = sbuf[fft][src ^ 1][1];
        const int idxD = (stage == 0) ? (j << 3)
                        : (stage == 1) ? (((j >> 3) << 6) + (j & 7))
                        : j;
        const int brev[8] = {0, 4, 2, 6, 1, 5, 3, 7};
        #pragma unroll
        for (int r = 0; r < 8; r++) {
            int a = PIDX(idxD + r * Ns);
            dre[a]  = vr[brev[r]];
            dim_[a] = vi[brev[r]];
        }
        src ^= 1;
        __syncthreads();
    }

    // ---- unpack two real spectra from packed complex FFT, write X.re / X.im ----
    {
        const float* re = sbuf[fft][1][0];
        const float* im = sbuf[fft][1][1];
        float* ob = out + ((size_t)b * TT + t) * ROW + fft * 2 * FDIM;
        #pragma unroll
        for (int k0 = 0; k0 < 5; k0++) {
            int k = j + k0 * 64;
            if (k <= 256) {
                int km = (512 - k) & 511;
                float a  = re[PIDX(k)],  bb_ = im[PIDX(k)];
                float c  = re[PIDX(km)], d   = im[PIDX(km)];
                ob[k]                    = 0.5f * (a + c);    // X_{2fft}  .re
                ob[FDIM + k]             = 0.5f * (bb_ + d);  // X_{2fft+1}.re
                ob[CC * FDIM + k]        = 0.5f * (bb_ - d);  // X_{2fft}  .im
                ob[CC * FDIM + FDIM + k] = 0.5f * (c - a);    // X_{2fft+1}.im
            }
        }
    }

    // ---- steering vector: straight copy of precomputed table ----
    {
        float* ob = out + ((size_t)b * TT + t) * ROW + 2 * CC * FDIM;
        #pragma unroll
        for (int i0 = 0; i0 < 17; i0++) {
            int i = tid + i0 * 128;
            if (i < SVLEN) ob[i] = g_sv[i];
        }
    }
}

extern "C" void kernel_launch(void* const* d_in, const int* in_sizes, int n_in,
                              void* d_out, int out_size) {
    const float* x       = (const float*)d_in[0];   // (16,4,160000)
    const float* angle   = (const float*)d_in[1];   // (16,1)
    const float* mic_pos = (const float*)d_in[2];   // (16,4,3)
    float* out = (float*)d_out;                     // (16,1251,4112)

    setup_kernel<<<1, 512>>>(angle, mic_pos);
    dim3 grid(TT, BB);
    sf_kernel<<<grid, 128>>>(x, out);
}

// round 12
// speedup vs baseline: 1.0135x; 1.0135x over previous
#include <cuda_runtime.h>
#include <math.h>

#define FDIM   257
#define BB     16
#define CC     4
#define LL     160000
#define TT     1251
#define HOPC   128
#define ROW    (4*CC*FDIM)          // 4112 floats per (b,t)
#define SVLEN  (2*CC*FDIM)          // 2056

__device__ float g_win[512];
__device__ float g_sv[SVLEN];

// ---------------- setup: window + steering-vector tables ----------------
__global__ void setup_kernel(const float* __restrict__ angle,
                             const float* __restrict__ mic_pos)
{
    __shared__ float sK[CC];
    int tid = threadIdx.x;

    if (tid < 512) {
        float cp = cosf((2.0f * (float)M_PI / 512.0f) * (float)tid);
        g_win[tid] = 0.5f * (1.0f - cp);
    }
    if (tid < CC) {
        const float half_pi = 1.57079632679489662f;
        float s90 = sinf(half_pi);
        float c90 = cosf(half_pi);
        float dc = 0.0f, d0 = 0.0f;
        #pragma unroll
        for (int bb = 0; bb < BB; bb++) {
            float rad = -angle[bb] * ((float)M_PI / 180.0f);
            float lx = cosf(rad) * s90;
            float ly = sinf(rad) * s90;
            float lz = c90;
            const float* mp0 = mic_pos + (bb * CC + 0) * 3;
            const float* mpc = mic_pos + (bb * CC + tid) * 3;
            float e;
            e = mp0[0] - lx; d0 += e * e;
            e = mp0[1] - ly; d0 += e * e;
            e = mp0[2] - lz; d0 += e * e;
            e = mpc[0] - lx; dc += e * e;
            e = mpc[1] - ly; dc += e * e;
            e = mpc[2] - lz; dc += e * e;
        }
        float tdoa = sqrtf(dc) - sqrtf(d0);
        sK[tid] = (-2.0f * (float)M_PI * 16000.0f / (512.0f * 340.4f)) * tdoa;
    }
    __syncthreads();

    for (int idx = tid; idx < SVLEN; idx += blockDim.x) {
        int reim = idx / (CC * FDIM);
        int rem  = idx - reim * (CC * FDIM);
        int c    = rem / FDIM;
        int f    = rem - c * FDIM;
        float s, co;
        sincosf(sK[c] * (float)f, &s, &co);
        g_sv[idx] = 0.5f * (reim ? s : co);
    }
}

// ---------------- main: 2x packed radix-8 Stockham FFT per (b,t) ----------------
#define PIDX(i) ((i) + ((i) >> 3))    // pad every 8 floats -> conflict-free stage writes
#define FFT2(ar,ai,br,bi) { float _tr=(ar), _ti=(ai); (ar)=_tr+(br); (ai)=_ti+(bi); (br)=_tr-(br); (bi)=_ti-(bi); }

__global__ __launch_bounds__(128) void sf_kernel(const float* __restrict__ x,
                                                 float* __restrict__ out)
{
    // [fft][pingpong][re/im][576]
    __shared__ float sbuf[2][2][2][576];

    const int t   = blockIdx.x;
    const int b   = blockIdx.y;
    const int tid = threadIdx.x;
    const int fft = tid >> 6;     // 0: channels 0,1   1: channels 2,3
    const int j   = tid & 63;

    // ---- load frame (reflect pad) * hann, packed: re=ch(2f), im=ch(2f+1) ----
    {
        const float* xc0 = x + ((size_t)(b * CC) + 2 * fft    ) * LL;
        const float* xc1 = x + ((size_t)(b * CC) + 2 * fft + 1) * LL;
        const int base = t * HOPC - 256;
        #pragma unroll
        for (int k = 0; k < 8; k++) {
            int p = j + k * 64;
            int idx = base + p;
            if (idx < 0)   idx = -idx;
            if (idx >= LL) idx = 2 * (LL - 1) - idx;
            float w = g_win[p];
            sbuf[fft][0][0][PIDX(p)] = xc0[idx] * w;
            sbuf[fft][0][1][PIDX(p)] = xc1[idx] * w;
        }
    }
    __syncthreads();

    // ---- 3-stage radix-8 Stockham (Ns = 1, 8, 64), ping-pong buffers ----
    float vr[8], vi[8];
    const float S2 = 0.70710678118654752f;
    int src = 0;

    #pragma unroll
    for (int stage = 0; stage < 3; stage++) {
        const int Ns = (stage == 0) ? 1 : (stage == 1) ? 8 : 64;

        const float* re = sbuf[fft][src][0];
        const float* im = sbuf[fft][src][1];
        #pragma unroll
        for (int r = 0; r < 8; r++) {
            int a = PIDX(j + r * 64);
            vr[r] = re[a];
            vi[r] = im[a];
        }

        if (stage > 0) {
            // v[r] *= exp(-2*pi*i * r * (j mod Ns) / (8*Ns)) via power recurrence
            float ang = (-2.0f * (float)M_PI / (8.0f * (float)Ns)) * (float)(j & (Ns - 1));
            float ws, wc;
            sincosf(ang, &ws, &wc);
            float cr = wc, ci = ws;
            #pragma unroll
            for (int r = 1; r < 8; r++) {
                float tr = vr[r] * cr - vi[r] * ci;
                float ti = vr[r] * ci + vi[r] * cr;
                vr[r] = tr; vi[r] = ti;
                float ncr = cr * wc - ci * ws;
                float nci = cr * ws + ci * wc;
                cr = ncr; ci = nci;
            }
        }

        // ---- in-register 8-point DIF FFT (output bit-reversed) ----
        FFT2(vr[0], vi[0], vr[4], vi[4]);
        FFT2(vr[1], vi[1], vr[5], vi[5]);
        FFT2(vr[2], vi[2], vr[6], vi[6]);
        FFT2(vr[3], vi[3], vr[7], vi[7]);
        { float tr = (vr[5] + vi[5]) * S2; float ti = (vi[5] - vr[5]) * S2; vr[5] = tr; vi[5] = ti; } // *W8^1
        { float tr = vi[6]; vi[6] = -vr[6]; vr[6] = tr; }                                             // *-i
        { float tr = (vi[7] - vr[7]) * S2; float ti = -(vr[7] + vi[7]) * S2; vr[7] = tr; vi[7] = ti; }// *W8^3
        FFT2(vr[0], vi[0], vr[2], vi[2]);
        FFT2(vr[1], vi[1], vr[3], vi[3]);
        FFT2(vr[4], vi[4], vr[6], vi[6]);
        FFT2(vr[5], vi[5], vr[7], vi[7]);
        { float tr = vi[3]; vi[3] = -vr[3]; vr[3] = tr; }
        { float tr = vi[7]; vi[7] = -vr[7]; vr[7] = tr; }
        FFT2(vr[0], vi[0], vr[1], vi[1]);
        FFT2(vr[2], vi[2], vr[3], vi[3]);
        FFT2(vr[4], vi[4], vr[5], vi[5]);
        FFT2(vr[6], vi[6], vr[7], vi[7]);

        // ---- scatter: dst[idxD + r*Ns] = X[r] = v[brev3(r)] ----
        float* dre = sbuf[fft][src ^ 1][0];
        float* dim_ = sbuf[fft][src ^ 1][1];
        const int idxD = (stage == 0) ? (j << 3)
                        : (stage == 1) ? (((j >> 3) << 6) + (j & 7))
                        : j;
        const int brev[8] = {0, 4, 2, 6, 1, 5, 3, 7};
        #pragma unroll
        for (int r = 0; r < 8; r++) {
            int a = PIDX(idxD + r * Ns);
            dre[a]  = vr[brev[r]];
            dim_[a] = vi[brev[r]];
        }
        src ^= 1;
        __syncthreads();
    }

    // ---- unpack two real spectra from packed complex FFT, write X.re / X.im ----
    {
        const float* re = sbuf[fft][1][0];
        const float* im = sbuf[fft][1][1];
        float* ob = out + ((size_t)b * TT + t) * ROW + fft * 2 * FDIM;
        #pragma unroll
        for (int k0 = 0; k0 < 5; k0++) {
            int k = j + k0 * 64;
            if (k <= 256) {
                int km = (512 - k) & 511;
                float a  = re[PIDX(k)],  bb_ = im[PIDX(k)];
                float c  = re[PIDX(km)], d   = im[PIDX(km)];
                ob[k]                    = 0.5f * (a + c);    // X_{2fft}  .re
                ob[FDIM + k]             = 0.5f * (bb_ + d);  // X_{2fft+1}.re
                ob[CC * FDIM + k]        = 0.5f * (bb_ - d);  // X_{2fft}  .im
                ob[CC * FDIM + FDIM + k] = 0.5f * (c - a);    // X_{2fft+1}.im
            }
        }
    }

    // ---- steering vector: straight copy of precomputed table ----
    {
        float* ob = out + ((size_t)b * TT + t) * ROW + 2 * CC * FDIM;
        #pragma unroll
        for (int i0 = 0; i0 < 17; i0++) {
            int i = tid + i0 * 128;
            if (i < SVLEN) ob[i] = g_sv[i];
        }
    }
}

extern "C" void kernel_launch(void* const* d_in, const int* in_sizes, int n_in,
                              void* d_out, int out_size) {
    const float* x       = (const float*)d_in[0];   // (16,4,160000)
    const float* angle   = (const float*)d_in[1];   // (16,1)
    const float* mic_pos = (const float*)d_in[2];   // (16,4,3)
    float* out = (float*)d_out;                     // (16,1251,4112)

    setup_kernel<<<1, 512>>>(angle, mic_pos);
    dim3 grid(TT, BB);
    sf_kernel<<<grid, 128>>>(x, out);
}